// round 15
// baseline (speedup 1.0000x reference)
#include <cuda_runtime.h>
#include <cuda_bf16.h>
#include <cstdint>

// VectorQuantize, GB300 (sm_103 base PTX: HMMA mma.sync path).
// Pinned-exact fp32 recipe (R4, rel_err==0):
//   dot  = single fp32 accumulator, FFMA, d ascending
//   dist = __fadd_rn(__fsub_rn(xsq, __fmul_rn(2.f, dot)), csq)
//   csq  = XLA warp row-reduce; argmin = first-min
// Phase1 = R9 mainloop + per-chunk-min (16 fp32/token) summary spill.
// Rescue v9: warp/token; candidate chunks = {ch: chunkmin < min + 1.0};
// exact-eval 64 codes per candidate chunk with pinned recipe.

#define DDIM    256
#define KCODES  1024
#define NMAX    65536
#define RESCUE_THRESH 0.75f
#define CHUNK_CUTOFF  1.0f
typedef unsigned long long ull;

__device__ float g_csq[KCODES];
__device__ float g_tokloss[NMAX];
__device__ int   g_bestidx[NMAX];
__device__ float g_chunkmin[(size_t)NMAX * 16];
__device__ int   g_rescue_list[NMAX];
__device__ int   g_rescue_cnt;
__device__ int   g_tile_ctr;
__device__ __nv_bfloat16 g_cbbf[KCODES * DDIM];

__device__ __forceinline__ uint32_t smem_u32(const void* p) {
    uint32_t a;
    asm("{ .reg .u64 t; cvta.to.shared.u64 t, %1; cvt.u32.u64 %0, t; }" : "=r"(a) : "l"(p));
    return a;
}
#define CP_ASYNC16(dst, src) \
    asm volatile("cp.async.cg.shared.global [%0], [%1], 16;" :: "r"(dst), "l"(src))
#define CP_COMMIT() asm volatile("cp.async.commit_group;" ::: "memory")
#define CP_WAIT0()  asm volatile("cp.async.wait_group 0;" ::: "memory")

__device__ __forceinline__ void ldmatrix_x4(uint32_t& r0, uint32_t& r1, uint32_t& r2,
                                            uint32_t& r3, uint32_t addr) {
    asm volatile("ldmatrix.sync.aligned.m8n8.x4.shared.b16 {%0,%1,%2,%3}, [%4];"
                 : "=r"(r0), "=r"(r1), "=r"(r2), "=r"(r3) : "r"(addr));
}
__device__ __forceinline__ void mma_bf16(float& c0, float& c1, float& c2, float& c3,
                                         uint32_t a0, uint32_t a1, uint32_t a2, uint32_t a3,
                                         uint32_t b0, uint32_t b1) {
    asm volatile("mma.sync.aligned.m16n8k16.row.col.f32.bf16.bf16.f32 "
                 "{%0,%1,%2,%3}, {%4,%5,%6,%7}, {%8,%9}, {%0,%1,%2,%3};"
                 : "+f"(c0), "+f"(c1), "+f"(c2), "+f"(c3)
                 : "r"(a0), "r"(a1), "r"(a2), "r"(a3), "r"(b0), "r"(b1));
}

// ---------------- csq + cb-bf16 + counters reset ----------------
__global__ void csq_kernel(const float* __restrict__ cb) {
    if (blockIdx.x == 0 && threadIdx.x == 0) { g_rescue_cnt = 0; g_tile_ctr = 0; }
    const int warp = (blockIdx.x * blockDim.x + threadIdx.x) >> 5;
    const int lane = threadIdx.x & 31;
    if (warp >= KCODES) return;
    const float* row = cb + (size_t)warp * DDIM;
    float p = 0.f;
#pragma unroll
    for (int i = 0; i < 8; i++) {
        float v = row[lane + i * 32];
        g_cbbf[(size_t)warp * DDIM + lane + i * 32] = __float2bfloat16(v);
        p = __fadd_rn(p, __fmul_rn(v, v));
    }
#pragma unroll
    for (int off = 16; off > 0; off >>= 1)
        p = __fadd_rn(p, __shfl_down_sync(0xffffffffu, p, off));
    if (lane == 0) g_csq[warp] = p;
}

// ---------------- phase 1 (R9 mainloop + chunk-min summary) ----------------
#define PA_OFF   0
#define PB_OFF   131072
#define PC_OFF   196608
#define PTILE_OFF 197120
#define PT_TOTAL 197136

__global__ void __launch_bounds__(256, 1) vq_phase1(const float* __restrict__ x, int ntiles) {
    extern __shared__ char smem[];
    const uint32_t sb = smem_u32(smem);
    int* s_tile = reinterpret_cast<int*>(smem + PTILE_OFF);
    const int tid  = threadIdx.x;
    const int w    = tid >> 5;
    const int lane = tid & 31;

    const int q  = lane >> 2;
    const int qi = lane & 3;
    const int l7 = lane & 7;
    const int bnsel = lane >> 4;
    const int bkoff = (lane >> 3) & 1;
    const int arow  = w * 32 + (lane & 15);
    const uint32_t abase0 = sb + PA_OFF + arow * 512;
    const uint32_t abase1 = abase0 + 16 * 512;
    const int asw   = arow & 7;
    const int akoff = lane >> 4;

    for (;;) {
        if (tid == 0) s_tile[0] = atomicAdd(&g_tile_ctr, 1);
        __syncthreads();
        const int tile = s_tile[0];
        __syncthreads();
        if (tile >= ntiles) break;
        const int tokenBase = tile * 256;

        {
            const char* bsrc = reinterpret_cast<const char*>(g_cbbf);
            for (int u = tid; u < 2048; u += 256) {
                int row = u >> 5, c = u & 31;
                CP_ASYNC16(sb + PB_OFF + row * 512 + ((c ^ (row & 7)) << 4),
                           bsrc + row * 512 + (c << 4));
            }
            if (tid < 16)
                CP_ASYNC16(sb + PC_OFF + tid * 16,
                           reinterpret_cast<const char*>(g_csq) + tid * 16);
            CP_COMMIT();
        }
        {
            const float* xsrc = x + (size_t)tokenBase * DDIM;
            for (int u = tid; u < 8192; u += 256) {
                int row = u >> 5, c = u & 31;
                const float4* p = reinterpret_cast<const float4*>(xsrc + row * DDIM + c * 8);
                float4 v0 = p[0], v1 = p[1];
                __nv_bfloat162 b0 = __floats2bfloat162_rn(v0.x, v0.y);
                __nv_bfloat162 b1 = __floats2bfloat162_rn(v0.z, v0.w);
                __nv_bfloat162 b2 = __floats2bfloat162_rn(v1.x, v1.y);
                __nv_bfloat162 b3 = __floats2bfloat162_rn(v1.z, v1.w);
                uint4 wv;
                wv.x = *reinterpret_cast<uint32_t*>(&b0);
                wv.y = *reinterpret_cast<uint32_t*>(&b1);
                wv.z = *reinterpret_cast<uint32_t*>(&b2);
                wv.w = *reinterpret_cast<uint32_t*>(&b3);
                *reinterpret_cast<uint4*>(smem + PA_OFF + row * 512 + ((c ^ (row & 7)) << 4)) = wv;
            }
        }
        CP_WAIT0();
        __syncthreads();

        float bv0 = 3.4e38f, sv0 = 3.4e38f, bv1 = 3.4e38f, sv1 = 3.4e38f;
        float bv2 = 3.4e38f, sv2 = 3.4e38f, bv3 = 3.4e38f, sv3 = 3.4e38f;
        int bi0 = 0, bi1 = 0, bi2 = 0, bi3 = 0;

        const int tb = tokenBase + w * 32;

        for (int ch = 0; ch < 16; ch++) {
            const uint32_t Bcur = sb + PB_OFF + (ch & 1) * 32768;
            const float*   csqs = reinterpret_cast<const float*>(smem + PC_OFF + (ch & 1) * 256);

            if (ch + 1 < 16) {
                const uint32_t Bnxt = sb + PB_OFF + ((ch + 1) & 1) * 32768;
                const char* bsrc = reinterpret_cast<const char*>(
                    g_cbbf + (size_t)(ch + 1) * 64 * DDIM);
                for (int u = tid; u < 2048; u += 256) {
                    int row = u >> 5, c = u & 31;
                    CP_ASYNC16(Bnxt + row * 512 + ((c ^ (row & 7)) << 4),
                               bsrc + row * 512 + (c << 4));
                }
                if (tid < 16)
                    CP_ASYNC16(sb + PC_OFF + ((ch + 1) & 1) * 256 + tid * 16,
                               reinterpret_cast<const char*>(g_csq + (ch + 1) * 64) + tid * 16);
                CP_COMMIT();
            }

            float acc[2][8][4];
#pragma unroll
            for (int h = 0; h < 2; h++)
#pragma unroll
                for (int nt = 0; nt < 8; nt++)
#pragma unroll
                    for (int j = 0; j < 4; j++) acc[h][nt][j] = 0.f;

#pragma unroll
            for (int ks = 0; ks < 16; ks++) {
                const uint32_t aoff = (uint32_t)(((2 * ks + akoff) ^ asw) << 4);
                uint32_t a00, a01, a02, a03, a10, a11, a12, a13;
                ldmatrix_x4(a00, a01, a02, a03, abase0 + aoff);
                ldmatrix_x4(a10, a11, a12, a13, abase1 + aoff);
#pragma unroll
                for (int ntp = 0; ntp < 4; ntp++) {
                    uint32_t b0, b1, b2, b3;
                    int brow = (ntp * 2 + bnsel) * 8 + l7;
                    ldmatrix_x4(b0, b1, b2, b3,
                                Bcur + brow * 512 + (((2 * ks + bkoff) ^ l7) << 4));
                    mma_bf16(acc[0][ntp*2][0], acc[0][ntp*2][1], acc[0][ntp*2][2], acc[0][ntp*2][3],
                             a00, a01, a02, a03, b0, b1);
                    mma_bf16(acc[0][ntp*2+1][0], acc[0][ntp*2+1][1], acc[0][ntp*2+1][2], acc[0][ntp*2+1][3],
                             a00, a01, a02, a03, b2, b3);
                    mma_bf16(acc[1][ntp*2][0], acc[1][ntp*2][1], acc[1][ntp*2][2], acc[1][ntp*2][3],
                             a10, a11, a12, a13, b0, b1);
                    mma_bf16(acc[1][ntp*2+1][0], acc[1][ntp*2+1][1], acc[1][ntp*2+1][2], acc[1][ntp*2+1][3],
                             a10, a11, a12, a13, b2, b3);
                }
            }

            float cm0 = 3.4e38f, cm1 = 3.4e38f, cm2 = 3.4e38f, cm3 = 3.4e38f;

#pragma unroll
            for (int nt = 0; nt < 8; nt++) {
                float2 cs = *reinterpret_cast<const float2*>(csqs + nt * 8 + 2 * qi);
                int code = ch * 64 + nt * 8 + 2 * qi;
                {
                    float d0 = __fmaf_rn(-2.0f, acc[0][nt][0], cs.x);
                    float d1 = __fmaf_rn(-2.0f, acc[0][nt][1], cs.y);
                    float d2 = __fmaf_rn(-2.0f, acc[0][nt][2], cs.x);
                    float d3 = __fmaf_rn(-2.0f, acc[0][nt][3], cs.y);
                    cm0 = fminf(cm0, fminf(d0, d1));
                    cm1 = fminf(cm1, fminf(d2, d3));
                    if (d0 < bv0) { sv0 = bv0; bv0 = d0; bi0 = code; } else if (d0 < sv0) sv0 = d0;
                    if (d1 < bv0) { sv0 = bv0; bv0 = d1; bi0 = code + 1; } else if (d1 < sv0) sv0 = d1;
                    if (d2 < bv1) { sv1 = bv1; bv1 = d2; bi1 = code; } else if (d2 < sv1) sv1 = d2;
                    if (d3 < bv1) { sv1 = bv1; bv1 = d3; bi1 = code + 1; } else if (d3 < sv1) sv1 = d3;
                }
                {
                    float d0 = __fmaf_rn(-2.0f, acc[1][nt][0], cs.x);
                    float d1 = __fmaf_rn(-2.0f, acc[1][nt][1], cs.y);
                    float d2 = __fmaf_rn(-2.0f, acc[1][nt][2], cs.x);
                    float d3 = __fmaf_rn(-2.0f, acc[1][nt][3], cs.y);
                    cm2 = fminf(cm2, fminf(d0, d1));
                    cm3 = fminf(cm3, fminf(d2, d3));
                    if (d0 < bv2) { sv2 = bv2; bv2 = d0; bi2 = code; } else if (d0 < sv2) sv2 = d0;
                    if (d1 < bv2) { sv2 = bv2; bv2 = d1; bi2 = code + 1; } else if (d1 < sv2) sv2 = d1;
                    if (d2 < bv3) { sv3 = bv3; bv3 = d2; bi3 = code; } else if (d2 < sv3) sv3 = d2;
                    if (d3 < bv3) { sv3 = bv3; bv3 = d3; bi3 = code + 1; } else if (d3 < sv3) sv3 = d3;
                }
            }

            // per-chunk quad reduce + summary store (1/4 threads, 4 STG.32)
            cm0 = fminf(cm0, __shfl_xor_sync(0xffffffffu, cm0, 1));
            cm0 = fminf(cm0, __shfl_xor_sync(0xffffffffu, cm0, 2));
            cm1 = fminf(cm1, __shfl_xor_sync(0xffffffffu, cm1, 1));
            cm1 = fminf(cm1, __shfl_xor_sync(0xffffffffu, cm1, 2));
            cm2 = fminf(cm2, __shfl_xor_sync(0xffffffffu, cm2, 1));
            cm2 = fminf(cm2, __shfl_xor_sync(0xffffffffu, cm2, 2));
            cm3 = fminf(cm3, __shfl_xor_sync(0xffffffffu, cm3, 1));
            cm3 = fminf(cm3, __shfl_xor_sync(0xffffffffu, cm3, 2));
            if (qi == 0) {
                g_chunkmin[(size_t)(tb + q) * 16 + ch]      = cm0;
                g_chunkmin[(size_t)(tb + q + 8) * 16 + ch]  = cm1;
                g_chunkmin[(size_t)(tb + q + 16) * 16 + ch] = cm2;
                g_chunkmin[(size_t)(tb + q + 24) * 16 + ch] = cm3;
            }

            CP_WAIT0();
            __syncthreads();
        }

#pragma unroll
        for (int m = 1; m <= 2; m <<= 1) {
            float ob, os; int oi;
            ob = __shfl_xor_sync(0xffffffffu, bv0, m); os = __shfl_xor_sync(0xffffffffu, sv0, m);
            oi = __shfl_xor_sync(0xffffffffu, bi0, m);
            if (ob < bv0 || (ob == bv0 && oi < bi0)) { sv0 = fminf(bv0, os); bv0 = ob; bi0 = oi; }
            else { sv0 = fminf(sv0, ob); }
            ob = __shfl_xor_sync(0xffffffffu, bv1, m); os = __shfl_xor_sync(0xffffffffu, sv1, m);
            oi = __shfl_xor_sync(0xffffffffu, bi1, m);
            if (ob < bv1 || (ob == bv1 && oi < bi1)) { sv1 = fminf(bv1, os); bv1 = ob; bi1 = oi; }
            else { sv1 = fminf(sv1, ob); }
            ob = __shfl_xor_sync(0xffffffffu, bv2, m); os = __shfl_xor_sync(0xffffffffu, sv2, m);
            oi = __shfl_xor_sync(0xffffffffu, bi2, m);
            if (ob < bv2 || (ob == bv2 && oi < bi2)) { sv2 = fminf(bv2, os); bv2 = ob; bi2 = oi; }
            else { sv2 = fminf(sv2, ob); }
            ob = __shfl_xor_sync(0xffffffffu, bv3, m); os = __shfl_xor_sync(0xffffffffu, sv3, m);
            oi = __shfl_xor_sync(0xffffffffu, bi3, m);
            if (ob < bv3 || (ob == bv3 && oi < bi3)) { sv3 = fminf(bv3, os); bv3 = ob; bi3 = oi; }
            else { sv3 = fminf(sv3, ob); }
        }

        if (qi == 0) {
            const int toks[4] = { tb + q, tb + q + 8, tb + 16 + q, tb + 24 + q };
            const float bvs[4] = { bv0, bv1, bv2, bv3 };
            const float svs[4] = { sv0, sv1, sv2, sv3 };
            const int   bis[4] = { bi0, bi1, bi2, bi3 };
#pragma unroll
            for (int s = 0; s < 4; s++) {
                g_bestidx[toks[s]] = bis[s];
                if (svs[s] - bvs[s] < RESCUE_THRESH) {
                    int p = atomicAdd(&g_rescue_cnt, 1);
                    if (p < NMAX) g_rescue_list[p] = toks[s];
                }
            }
        }
        __syncthreads();
    }
}

// ---------------- exact rescue v9: warp/token, candidate chunks from chunkmin ----
__global__ void __launch_bounds__(256) rescue_kernel(
    const float* __restrict__ x, const float* __restrict__ cb)
{
    __shared__ float4 xs4[8][65];
    __shared__ float  xqs[8];

    const int tid = threadIdx.x;
    const int warp = tid >> 5, lane = tid & 31;
    int cnt = g_rescue_cnt;
    if (cnt > NMAX) cnt = NMAX;

    for (int e = blockIdx.x * 8 + warp; e < cnt; e += gridDim.x * 8) {
        const int tok = g_rescue_list[e];
        const float4* xr = reinterpret_cast<const float4*>(x + (size_t)tok * DDIM);
        xs4[warp][lane]      = xr[lane];
        xs4[warp][lane + 32] = xr[lane + 32];
        __syncwarp();
        if (lane == 0) {   // pinned xsq: same source text as R4
            const float* row = reinterpret_cast<const float*>(xs4[warp]);
            float s = 0.f;
#pragma unroll 8
            for (int d = 0; d < DDIM; d++) s += row[d] * row[d];
            xqs[warp] = s;
        }
        __syncwarp();
        const float xq = xqs[warp];

        // candidate chunks
        float cm = (lane < 16) ? __ldg(&g_chunkmin[(size_t)tok * 16 + lane]) : 3.4e38f;
        float mn = cm;
#pragma unroll
        for (int off = 16; off > 0; off >>= 1)
            mn = fminf(mn, __shfl_xor_sync(0xffffffffu, mn, off));
        unsigned mask = __ballot_sync(0xffffffffu, cm < mn + CHUNK_CUTOFF) & 0xffffu;

        // exact-eval: 2 codes/lane per candidate chunk, pinned recipe
        ull best = ~0ull;
        while (mask) {
            const int ch = __ffs(mask) - 1;
            mask &= mask - 1;
            const int k0 = ch * 64 + lane * 2;
            const float4* c0 = reinterpret_cast<const float4*>(cb + (size_t)k0 * DDIM);
            const float4* c1 = reinterpret_cast<const float4*>(cb + (size_t)(k0 + 1) * DDIM);
            float a0 = 0.f, a1 = 0.f;
#pragma unroll 4
            for (int i = 0; i < 64; i++) {
                float4 xv = xs4[warp][i];
                float4 u = __ldg(c0 + i), v = __ldg(c1 + i);
                a0 = __fmaf_rn(xv.x, u.x, a0); a1 = __fmaf_rn(xv.x, v.x, a1);
                a0 = __fmaf_rn(xv.y, u.y, a0); a1 = __fmaf_rn(xv.y, v.y, a1);
                a0 = __fmaf_rn(xv.z, u.z, a0); a1 = __fmaf_rn(xv.z, v.z, a1);
                a0 = __fmaf_rn(xv.w, u.w, a0); a1 = __fmaf_rn(xv.w, v.w, a1);
            }
            float d0 = __fadd_rn(__fsub_rn(xq, __fmul_rn(2.0f, a0)), g_csq[k0]);
            float d1 = __fadd_rn(__fsub_rn(xq, __fmul_rn(2.0f, a1)), g_csq[k0 + 1]);
            ull p0 = ((ull)__float_as_uint(d0) << 32) | (unsigned)k0;
            ull p1 = ((ull)__float_as_uint(d1) << 32) | (unsigned)(k0 + 1);
            if (p0 < best) best = p0;
            if (p1 < best) best = p1;
        }
#pragma unroll
        for (int off = 16; off > 0; off >>= 1) {
            ull o = __shfl_xor_sync(0xffffffffu, best, off);
            if (o < best) best = o;
        }
        if (lane == 0) g_bestidx[tok] = (int)(best & 0xffffffffull);
        __syncwarp();
    }
}

// ---------------- gather + STE + loss ----------------
__global__ void __launch_bounds__(256) gather_kernel(
    const float* __restrict__ x, const float* __restrict__ cb,
    float* __restrict__ out, float* __restrict__ oidx)
{
    const int token = (blockIdx.x * 256 + threadIdx.x) >> 5;
    const int lane = threadIdx.x & 31;
    const int k = g_bestidx[token];
    if (lane == 0 && oidx) oidx[token] = (float)k;
    const float4* xr = reinterpret_cast<const float4*>(x + (size_t)token * DDIM);
    const float4* qr = reinterpret_cast<const float4*>(cb + (size_t)k * DDIM);
    float4* orow = reinterpret_cast<float4*>(out + (size_t)token * DDIM);
    float s = 0.f;
#pragma unroll
    for (int h = 0; h < 2; h++) {
        int i = h * 32 + lane;
        float4 xv = xr[i], qv = qr[i];
        float4 o;
        o.x = xv.x + (qv.x - xv.x);
        o.y = xv.y + (qv.y - xv.y);
        o.z = xv.z + (qv.z - xv.z);
        o.w = xv.w + (qv.w - xv.w);
        orow[i] = o;
        float dx = xv.x - qv.x, dy = xv.y - qv.y, dz = xv.z - qv.z, dw = xv.w - qv.w;
        s += dx * dx + dy * dy + dz * dz + dw * dw;
    }
#pragma unroll
    for (int off = 16; off > 0; off >>= 1)
        s += __shfl_down_sync(0xffffffffu, s, off);
    if (lane == 0) g_tokloss[token] = s;
}

__global__ void loss_final(float* __restrict__ out_loss, float inv, int n) {
    __shared__ float red[1024];
    const int tid = threadIdx.x;
    float s = 0.f;
    for (int i = tid; i < n; i += 1024) s += g_tokloss[i];
    red[tid] = s;
    __syncthreads();
    for (int off = 512; off > 0; off >>= 1) {
        if (tid < off) red[tid] += red[tid + off];
        __syncthreads();
    }
    if (tid == 0) *out_loss = red[0] * inv;
}

extern "C" void kernel_launch(void* const* d_in, const int* in_sizes, int n_in,
                              void* d_out, int out_size)
{
    const float* x  = (const float*)d_in[0];
    const float* cb = (const float*)d_in[1];
    const long long n_elems = (long long)in_sizes[0];   // N * 256
    const int N = (int)(n_elems / DDIM);
    const int ntiles = N / 256;

    float* out   = (float*)d_out;
    float* oidx  = nullptr;
    float* oloss = nullptr;
    const long long need_idx = n_elems + N;
    if ((long long)out_size >= need_idx)      oidx  = out + n_elems;
    if ((long long)out_size >= need_idx + 1)  oloss = out + need_idx;
    else if ((long long)out_size == n_elems + 1) oloss = out + n_elems;

    cudaFuncSetAttribute(vq_phase1, cudaFuncAttributeMaxDynamicSharedMemorySize, PT_TOTAL);

    csq_kernel<<<(KCODES * 32 + 255) / 256, 256>>>(cb);
    vq_phase1<<<148, 256, PT_TOTAL>>>(x, ntiles);
    rescue_kernel<<<296, 256>>>(x, cb);
    gather_kernel<<<N / 8, 256>>>(x, cb, out, oidx);
    if (oloss) loss_final<<<1, 1024>>>(oloss, 1.0f / ((float)N * (float)DDIM), N);
}

// round 16
// speedup vs baseline: 1.6416x; 1.6416x over previous
#include <cuda_runtime.h>
#include <cuda_bf16.h>
#include <cuda_fp16.h>
#include <cstdint>

// VectorQuantize, GB300 (sm_103 base PTX: HMMA mma.sync path).
// Pinned-exact fp32 recipe (R4, rel_err==0):
//   dot  = single fp32 accumulator, FFMA, d ascending
//   dist = __fadd_rn(__fsub_rn(xsq, __fmul_rn(2.f, dot)), csq)
//   csq  = XLA warp row-reduce; argmin = first-min
// Phase1 = R14 (218.7us, passed) with score spill packed to STG.128:
//   slot = ch*32 + qi*8 + nt  (contiguous per row per chunk).
// Rescue v8b: candidates = {k: d~(k) < d~min + 1.25} from spilled scores
// (new slot->code map); exact-eval candidates with pinned recipe.

#define DDIM    256
#define KCODES  1024
#define NMAX    65536
#define RESCUE_THRESH 0.75f
#define CAND_CUTOFF   1.25f
typedef unsigned long long ull;

__device__ float g_csq[KCODES];
__device__ float g_tokloss[NMAX];
__device__ int   g_bestidx[NMAX];
__device__ int   g_rescue_list[NMAX];
__device__ int   g_rescue_cnt;
__device__ int   g_tile_ctr;
__device__ __nv_bfloat16 g_cbbf[KCODES * DDIM];
__device__ __half2 g_scores[(size_t)NMAX * 512];   // [token][slot] fp16 scores

__device__ __forceinline__ uint32_t smem_u32(const void* p) {
    uint32_t a;
    asm("{ .reg .u64 t; cvta.to.shared.u64 t, %1; cvt.u32.u64 %0, t; }" : "=r"(a) : "l"(p));
    return a;
}
#define CP_ASYNC16(dst, src) \
    asm volatile("cp.async.cg.shared.global [%0], [%1], 16;" :: "r"(dst), "l"(src))
#define CP_COMMIT() asm volatile("cp.async.commit_group;" ::: "memory")
#define CP_WAIT0()  asm volatile("cp.async.wait_group 0;" ::: "memory")

__device__ __forceinline__ void ldmatrix_x4(uint32_t& r0, uint32_t& r1, uint32_t& r2,
                                            uint32_t& r3, uint32_t addr) {
    asm volatile("ldmatrix.sync.aligned.m8n8.x4.shared.b16 {%0,%1,%2,%3}, [%4];"
                 : "=r"(r0), "=r"(r1), "=r"(r2), "=r"(r3) : "r"(addr));
}
__device__ __forceinline__ void mma_bf16(float& c0, float& c1, float& c2, float& c3,
                                         uint32_t a0, uint32_t a1, uint32_t a2, uint32_t a3,
                                         uint32_t b0, uint32_t b1) {
    asm volatile("mma.sync.aligned.m16n8k16.row.col.f32.bf16.bf16.f32 "
                 "{%0,%1,%2,%3}, {%4,%5,%6,%7}, {%8,%9}, {%0,%1,%2,%3};"
                 : "+f"(c0), "+f"(c1), "+f"(c2), "+f"(c3)
                 : "r"(a0), "r"(a1), "r"(a2), "r"(a3), "r"(b0), "r"(b1));
}
__device__ __forceinline__ uint32_t packh2(float a, float b) {
    __half2 h = __floats2half2_rn(a, b);
    return *reinterpret_cast<uint32_t*>(&h);
}

// ---------------- csq + cb-bf16 + counters reset ----------------
__global__ void csq_kernel(const float* __restrict__ cb) {
    if (blockIdx.x == 0 && threadIdx.x == 0) { g_rescue_cnt = 0; g_tile_ctr = 0; }
    const int warp = (blockIdx.x * blockDim.x + threadIdx.x) >> 5;
    const int lane = threadIdx.x & 31;
    if (warp >= KCODES) return;
    const float* row = cb + (size_t)warp * DDIM;
    float p = 0.f;
#pragma unroll
    for (int i = 0; i < 8; i++) {
        float v = row[lane + i * 32];
        g_cbbf[(size_t)warp * DDIM + lane + i * 32] = __float2bfloat16(v);
        p = __fadd_rn(p, __fmul_rn(v, v));
    }
#pragma unroll
    for (int off = 16; off > 0; off >>= 1)
        p = __fadd_rn(p, __shfl_down_sync(0xffffffffu, p, off));
    if (lane == 0) g_csq[warp] = p;
}

// ---------------- phase 1 (R9 mainloop + packed score spill) ----------------
#define PA_OFF   0
#define PB_OFF   131072
#define PC_OFF   196608
#define PTILE_OFF 197120
#define PT_TOTAL 197136

__global__ void __launch_bounds__(256, 1) vq_phase1(const float* __restrict__ x, int ntiles) {
    extern __shared__ char smem[];
    const uint32_t sb = smem_u32(smem);
    int* s_tile = reinterpret_cast<int*>(smem + PTILE_OFF);
    const int tid  = threadIdx.x;
    const int w    = tid >> 5;
    const int lane = tid & 31;

    const int q  = lane >> 2;
    const int qi = lane & 3;
    const int l7 = lane & 7;
    const int bnsel = lane >> 4;
    const int bkoff = (lane >> 3) & 1;
    const int arow  = w * 32 + (lane & 15);
    const uint32_t abase0 = sb + PA_OFF + arow * 512;
    const uint32_t abase1 = abase0 + 16 * 512;
    const int asw   = arow & 7;
    const int akoff = lane >> 4;

    for (;;) {
        if (tid == 0) s_tile[0] = atomicAdd(&g_tile_ctr, 1);
        __syncthreads();
        const int tile = s_tile[0];
        __syncthreads();
        if (tile >= ntiles) break;
        const int tokenBase = tile * 256;

        {
            const char* bsrc = reinterpret_cast<const char*>(g_cbbf);
            for (int u = tid; u < 2048; u += 256) {
                int row = u >> 5, c = u & 31;
                CP_ASYNC16(sb + PB_OFF + row * 512 + ((c ^ (row & 7)) << 4),
                           bsrc + row * 512 + (c << 4));
            }
            if (tid < 16)
                CP_ASYNC16(sb + PC_OFF + tid * 16,
                           reinterpret_cast<const char*>(g_csq) + tid * 16);
            CP_COMMIT();
        }
        {
            const float* xsrc = x + (size_t)tokenBase * DDIM;
            for (int u = tid; u < 8192; u += 256) {
                int row = u >> 5, c = u & 31;
                const float4* p = reinterpret_cast<const float4*>(xsrc + row * DDIM + c * 8);
                float4 v0 = p[0], v1 = p[1];
                __nv_bfloat162 b0 = __floats2bfloat162_rn(v0.x, v0.y);
                __nv_bfloat162 b1 = __floats2bfloat162_rn(v0.z, v0.w);
                __nv_bfloat162 b2 = __floats2bfloat162_rn(v1.x, v1.y);
                __nv_bfloat162 b3 = __floats2bfloat162_rn(v1.z, v1.w);
                uint4 wv;
                wv.x = *reinterpret_cast<uint32_t*>(&b0);
                wv.y = *reinterpret_cast<uint32_t*>(&b1);
                wv.z = *reinterpret_cast<uint32_t*>(&b2);
                wv.w = *reinterpret_cast<uint32_t*>(&b3);
                *reinterpret_cast<uint4*>(smem + PA_OFF + row * 512 + ((c ^ (row & 7)) << 4)) = wv;
            }
        }
        CP_WAIT0();
        __syncthreads();

        float bv0 = 3.4e38f, sv0 = 3.4e38f, bv1 = 3.4e38f, sv1 = 3.4e38f;
        float bv2 = 3.4e38f, sv2 = 3.4e38f, bv3 = 3.4e38f, sv3 = 3.4e38f;
        int bi0 = 0, bi1 = 0, bi2 = 0, bi3 = 0;

        // uint4 score-row bases for this thread's 4 tokens
        uint4* const srL0 = reinterpret_cast<uint4*>(
            g_scores + (size_t)(tokenBase + w * 32 + q) * 512);
        uint4* const srH0 = srL0 + (8 * 512 / 4);
        uint4* const srL1 = srL0 + (16 * 512 / 4);
        uint4* const srH1 = srL0 + (24 * 512 / 4);

        for (int ch = 0; ch < 16; ch++) {
            const uint32_t Bcur = sb + PB_OFF + (ch & 1) * 32768;
            const float*   csqs = reinterpret_cast<const float*>(smem + PC_OFF + (ch & 1) * 256);

            if (ch + 1 < 16) {
                const uint32_t Bnxt = sb + PB_OFF + ((ch + 1) & 1) * 32768;
                const char* bsrc = reinterpret_cast<const char*>(
                    g_cbbf + (size_t)(ch + 1) * 64 * DDIM);
                for (int u = tid; u < 2048; u += 256) {
                    int row = u >> 5, c = u & 31;
                    CP_ASYNC16(Bnxt + row * 512 + ((c ^ (row & 7)) << 4),
                               bsrc + row * 512 + (c << 4));
                }
                if (tid < 16)
                    CP_ASYNC16(sb + PC_OFF + ((ch + 1) & 1) * 256 + tid * 16,
                               reinterpret_cast<const char*>(g_csq + (ch + 1) * 64) + tid * 16);
                CP_COMMIT();
            }

            float acc[2][8][4];
#pragma unroll
            for (int h = 0; h < 2; h++)
#pragma unroll
                for (int nt = 0; nt < 8; nt++)
#pragma unroll
                    for (int j = 0; j < 4; j++) acc[h][nt][j] = 0.f;

#pragma unroll
            for (int ks = 0; ks < 16; ks++) {
                const uint32_t aoff = (uint32_t)(((2 * ks + akoff) ^ asw) << 4);
                uint32_t a00, a01, a02, a03, a10, a11, a12, a13;
                ldmatrix_x4(a00, a01, a02, a03, abase0 + aoff);
                ldmatrix_x4(a10, a11, a12, a13, abase1 + aoff);
#pragma unroll
                for (int ntp = 0; ntp < 4; ntp++) {
                    uint32_t b0, b1, b2, b3;
                    int brow = (ntp * 2 + bnsel) * 8 + l7;
                    ldmatrix_x4(b0, b1, b2, b3,
                                Bcur + brow * 512 + (((2 * ks + bkoff) ^ l7) << 4));
                    mma_bf16(acc[0][ntp*2][0], acc[0][ntp*2][1], acc[0][ntp*2][2], acc[0][ntp*2][3],
                             a00, a01, a02, a03, b0, b1);
                    mma_bf16(acc[0][ntp*2+1][0], acc[0][ntp*2+1][1], acc[0][ntp*2+1][2], acc[0][ntp*2+1][3],
                             a00, a01, a02, a03, b2, b3);
                    mma_bf16(acc[1][ntp*2][0], acc[1][ntp*2][1], acc[1][ntp*2][2], acc[1][ntp*2][3],
                             a10, a11, a12, a13, b0, b1);
                    mma_bf16(acc[1][ntp*2+1][0], acc[1][ntp*2+1][1], acc[1][ntp*2+1][2], acc[1][ntp*2+1][3],
                             a10, a11, a12, a13, b2, b3);
                }
            }

            // epilogue: spill (packed STG.128) + running top-2
#pragma unroll
            for (int hf = 0; hf < 2; hf++) {
                uint32_t vL0[4], vH0[4], vL1[4], vH1[4];
#pragma unroll
                for (int j = 0; j < 4; j++) {
                    const int nt = hf * 4 + j;
                    float2 cs = *reinterpret_cast<const float2*>(csqs + nt * 8 + 2 * qi);
                    int code = ch * 64 + nt * 8 + 2 * qi;
                    vL0[j] = packh2(acc[0][nt][0], acc[0][nt][1]);
                    vH0[j] = packh2(acc[0][nt][2], acc[0][nt][3]);
                    vL1[j] = packh2(acc[1][nt][0], acc[1][nt][1]);
                    vH1[j] = packh2(acc[1][nt][2], acc[1][nt][3]);
                    {
                        float d0 = __fmaf_rn(-2.0f, acc[0][nt][0], cs.x);
                        float d1 = __fmaf_rn(-2.0f, acc[0][nt][1], cs.y);
                        float d2 = __fmaf_rn(-2.0f, acc[0][nt][2], cs.x);
                        float d3 = __fmaf_rn(-2.0f, acc[0][nt][3], cs.y);
                        if (d0 < bv0) { sv0 = bv0; bv0 = d0; bi0 = code; } else if (d0 < sv0) sv0 = d0;
                        if (d1 < bv0) { sv0 = bv0; bv0 = d1; bi0 = code + 1; } else if (d1 < sv0) sv0 = d1;
                        if (d2 < bv1) { sv1 = bv1; bv1 = d2; bi1 = code; } else if (d2 < sv1) sv1 = d2;
                        if (d3 < bv1) { sv1 = bv1; bv1 = d3; bi1 = code + 1; } else if (d3 < sv1) sv1 = d3;
                    }
                    {
                        float d0 = __fmaf_rn(-2.0f, acc[1][nt][0], cs.x);
                        float d1 = __fmaf_rn(-2.0f, acc[1][nt][1], cs.y);
                        float d2 = __fmaf_rn(-2.0f, acc[1][nt][2], cs.x);
                        float d3 = __fmaf_rn(-2.0f, acc[1][nt][3], cs.y);
                        if (d0 < bv2) { sv2 = bv2; bv2 = d0; bi2 = code; } else if (d0 < sv2) sv2 = d0;
                        if (d1 < bv2) { sv2 = bv2; bv2 = d1; bi2 = code + 1; } else if (d1 < sv2) sv2 = d1;
                        if (d2 < bv3) { sv3 = bv3; bv3 = d2; bi3 = code; } else if (d2 < sv3) sv3 = d2;
                        if (d3 < bv3) { sv3 = bv3; bv3 = d3; bi3 = code + 1; } else if (d3 < sv3) sv3 = d3;
                    }
                }
                const int u4i = ch * 8 + qi * 2 + hf;   // slot = ch*32 + qi*8 + hf*4 (+j)
                srL0[u4i] = make_uint4(vL0[0], vL0[1], vL0[2], vL0[3]);
                srH0[u4i] = make_uint4(vH0[0], vH0[1], vH0[2], vH0[3]);
                srL1[u4i] = make_uint4(vL1[0], vL1[1], vL1[2], vL1[3]);
                srH1[u4i] = make_uint4(vH1[0], vH1[1], vH1[2], vH1[3]);
            }

            CP_WAIT0();
            __syncthreads();
        }

#pragma unroll
        for (int m = 1; m <= 2; m <<= 1) {
            float ob, os; int oi;
            ob = __shfl_xor_sync(0xffffffffu, bv0, m); os = __shfl_xor_sync(0xffffffffu, sv0, m);
            oi = __shfl_xor_sync(0xffffffffu, bi0, m);
            if (ob < bv0 || (ob == bv0 && oi < bi0)) { sv0 = fminf(bv0, os); bv0 = ob; bi0 = oi; }
            else { sv0 = fminf(sv0, ob); }
            ob = __shfl_xor_sync(0xffffffffu, bv1, m); os = __shfl_xor_sync(0xffffffffu, sv1, m);
            oi = __shfl_xor_sync(0xffffffffu, bi1, m);
            if (ob < bv1 || (ob == bv1 && oi < bi1)) { sv1 = fminf(bv1, os); bv1 = ob; bi1 = oi; }
            else { sv1 = fminf(sv1, ob); }
            ob = __shfl_xor_sync(0xffffffffu, bv2, m); os = __shfl_xor_sync(0xffffffffu, sv2, m);
            oi = __shfl_xor_sync(0xffffffffu, bi2, m);
            if (ob < bv2 || (ob == bv2 && oi < bi2)) { sv2 = fminf(bv2, os); bv2 = ob; bi2 = oi; }
            else { sv2 = fminf(sv2, ob); }
            ob = __shfl_xor_sync(0xffffffffu, bv3, m); os = __shfl_xor_sync(0xffffffffu, sv3, m);
            oi = __shfl_xor_sync(0xffffffffu, bi3, m);
            if (ob < bv3 || (ob == bv3 && oi < bi3)) { sv3 = fminf(bv3, os); bv3 = ob; bi3 = oi; }
            else { sv3 = fminf(sv3, ob); }
        }

        if (qi == 0) {
            const int tb = tokenBase + w * 32;
            const int toks[4] = { tb + q, tb + q + 8, tb + 16 + q, tb + 24 + q };
            const float bvs[4] = { bv0, bv1, bv2, bv3 };
            const float svs[4] = { sv0, sv1, sv2, sv3 };
            const int   bis[4] = { bi0, bi1, bi2, bi3 };
#pragma unroll
            for (int s = 0; s < 4; s++) {
                g_bestidx[toks[s]] = bis[s];
                if (svs[s] - bvs[s] < RESCUE_THRESH) {
                    int p = atomicAdd(&g_rescue_cnt, 1);
                    if (p < NMAX) g_rescue_list[p] = toks[s];
                }
            }
        }
        __syncthreads();
    }
}

// ---------------- exact rescue v8b: candidates from spilled scores (new map) ----
// slot s = ch*32 + qi*8 + nt holds half2 of codes (ch*64 + nt*8 + 2qi, +1).
// Lane owns slots [lane*16, lane*16+16): code_pair(m') = base + (m'&7)*8 + (m'>>3)*2,
// base = (lane>>1)*64 + (lane&1)*4, m' = 0..15.
__global__ void __launch_bounds__(256) rescue_kernel(
    const float* __restrict__ x, const float* __restrict__ cb)
{
    __shared__ float4 xs4[8][65];
    __shared__ float  xqs[8];
    __shared__ int    cand[8][64];
    __shared__ float  csq_s[KCODES];

    const int tid = threadIdx.x;
    const int warp = tid >> 5, lane = tid & 31;
    for (int i = tid; i < KCODES; i += 256) csq_s[i] = g_csq[i];
    __syncthreads();

    int cnt = g_rescue_cnt;
    if (cnt > NMAX) cnt = NMAX;
    const int base = (lane >> 1) * 64 + (lane & 1) * 4;

    for (int e = blockIdx.x * 8 + warp; e < cnt; e += gridDim.x * 8) {
        const int tok = g_rescue_list[e];
        const float4* xr = reinterpret_cast<const float4*>(x + (size_t)tok * DDIM);
        xs4[warp][lane]      = xr[lane];
        xs4[warp][lane + 32] = xr[lane + 32];
        __syncwarp();
        if (lane == 0) {   // pinned xsq: same source text as R4
            const float* row = reinterpret_cast<const float*>(xs4[warp]);
            float s = 0.f;
#pragma unroll 8
            for (int d = 0; d < DDIM; d++) s += row[d] * row[d];
            xqs[warp] = s;
        }
        __syncwarp();
        const float xq = xqs[warp];

        // rebuild this lane's 32 approx dists
        float dv[32];
        {
            const uint4* sp = reinterpret_cast<const uint4*>(
                g_scores + (size_t)tok * 512) + lane * 4;
#pragma unroll
            for (int b = 0; b < 4; b++) {
                uint4 sv = __ldg(sp + b);
                const uint32_t uw[4] = { sv.x, sv.y, sv.z, sv.w };
#pragma unroll
                for (int j = 0; j < 4; j++) {
                    const int mp = b * 4 + j;
                    const int cp = base + (mp & 7) * 8 + (mp >> 3) * 2;
                    __half2 h = *reinterpret_cast<const __half2*>(&uw[j]);
                    float2 f = __half22float2(h);
                    dv[2 * mp]     = __fmaf_rn(-2.0f, f.x, csq_s[cp]);
                    dv[2 * mp + 1] = __fmaf_rn(-2.0f, f.y, csq_s[cp + 1]);
                }
            }
        }
        float mn = dv[0];
#pragma unroll
        for (int m = 1; m < 32; m++) mn = fminf(mn, dv[m]);
#pragma unroll
        for (int off = 16; off > 0; off >>= 1)
            mn = fminf(mn, __shfl_xor_sync(0xffffffffu, mn, off));
        const float T = mn + CAND_CUTOFF;

        // collect candidate codes
        int nb = 0;
#pragma unroll
        for (int i = 0; i < 32; i++) {
            bool c = dv[i] < T;
            unsigned msk = __ballot_sync(0xffffffffu, c);
            if (c) {
                const int mp = i >> 1;
                const int code = base + (mp & 7) * 8 + (mp >> 3) * 2 + (i & 1);
                int slot = nb + __popc(msk & ((1u << lane) - 1));
                if (slot < 64) cand[warp][slot] = code;
            }
            nb += __popc(msk);
        }
        __syncwarp();
        const int nc = nb < 64 ? nb : 64;

        // exact-eval candidates (pinned recipe), packed-key first-min
        ull best = ~0ull;
        for (int c = lane; c < nc; c += 32) {
            const int k = cand[warp][c];
            const float4* cr = reinterpret_cast<const float4*>(cb + (size_t)k * DDIM);
            float a = 0.f;
#pragma unroll 4
            for (int i = 0; i < 64; i++) {
                float4 xv = xs4[warp][i];
                float4 u = __ldg(cr + i);
                a = __fmaf_rn(xv.x, u.x, a);
                a = __fmaf_rn(xv.y, u.y, a);
                a = __fmaf_rn(xv.z, u.z, a);
                a = __fmaf_rn(xv.w, u.w, a);
            }
            float dd = __fadd_rn(__fsub_rn(xq, __fmul_rn(2.0f, a)), csq_s[k]);
            ull key = ((ull)__float_as_uint(dd) << 32) | (unsigned)k;
            if (key < best) best = key;
        }
#pragma unroll
        for (int off = 16; off > 0; off >>= 1) {
            ull o = __shfl_xor_sync(0xffffffffu, best, off);
            if (o < best) best = o;
        }
        if (lane == 0 && nc > 0) g_bestidx[tok] = (int)(best & 0xffffffffull);
        __syncwarp();
    }
}

// ---------------- gather + STE + loss ----------------
__global__ void __launch_bounds__(256) gather_kernel(
    const float* __restrict__ x, const float* __restrict__ cb,
    float* __restrict__ out, float* __restrict__ oidx)
{
    const int token = (blockIdx.x * 256 + threadIdx.x) >> 5;
    const int lane = threadIdx.x & 31;
    const int k = g_bestidx[token];
    if (lane == 0 && oidx) oidx[token] = (float)k;
    const float4* xr = reinterpret_cast<const float4*>(x + (size_t)token * DDIM);
    const float4* qr = reinterpret_cast<const float4*>(cb + (size_t)k * DDIM);
    float4* orow = reinterpret_cast<float4*>(out + (size_t)token * DDIM);
    float s = 0.f;
#pragma unroll
    for (int h = 0; h < 2; h++) {
        int i = h * 32 + lane;
        float4 xv = xr[i], qv = qr[i];
        float4 o;
        o.x = xv.x + (qv.x - xv.x);
        o.y = xv.y + (qv.y - xv.y);
        o.z = xv.z + (qv.z - xv.z);
        o.w = xv.w + (qv.w - xv.w);
        orow[i] = o;
        float dx = xv.x - qv.x, dy = xv.y - qv.y, dz = xv.z - qv.z, dw = xv.w - qv.w;
        s += dx * dx + dy * dy + dz * dz + dw * dw;
    }
#pragma unroll
    for (int off = 16; off > 0; off >>= 1)
        s += __shfl_down_sync(0xffffffffu, s, off);
    if (lane == 0) g_tokloss[token] = s;
}

__global__ void loss_final(float* __restrict__ out_loss, float inv, int n) {
    __shared__ float red[1024];
    const int tid = threadIdx.x;
    float s = 0.f;
    for (int i = tid; i < n; i += 1024) s += g_tokloss[i];
    red[tid] = s;
    __syncthreads();
    for (int off = 512; off > 0; off >>= 1) {
        if (tid < off) red[tid] += red[tid + off];
        __syncthreads();
    }
    if (tid == 0) *out_loss = red[0] * inv;
}

extern "C" void kernel_launch(void* const* d_in, const int* in_sizes, int n_in,
                              void* d_out, int out_size)
{
    const float* x  = (const float*)d_in[0];
    const float* cb = (const float*)d_in[1];
    const long long n_elems = (long long)in_sizes[0];   // N * 256
    const int N = (int)(n_elems / DDIM);
    const int ntiles = N / 256;

    float* out   = (float*)d_out;
    float* oidx  = nullptr;
    float* oloss = nullptr;
    const long long need_idx = n_elems + N;
    if ((long long)out_size >= need_idx)      oidx  = out + n_elems;
    if ((long long)out_size >= need_idx + 1)  oloss = out + need_idx;
    else if ((long long)out_size == n_elems + 1) oloss = out + n_elems;

    cudaFuncSetAttribute(vq_phase1, cudaFuncAttributeMaxDynamicSharedMemorySize, PT_TOTAL);

    csq_kernel<<<(KCODES * 32 + 255) / 256, 256>>>(cb);
    vq_phase1<<<148, 256, PT_TOTAL>>>(x, ntiles);
    rescue_kernel<<<296, 256>>>(x, cb);
    gather_kernel<<<N / 8, 256>>>(x, cb, out, oidx);
    if (oloss) loss_final<<<1, 1024>>>(oloss, 1.0f / ((float)N * (float)DDIM), N);
}